// round 14
// baseline (speedup 1.0000x reference)
#include <cuda_runtime.h>
#include <cuda_fp16.h>
#include <cuda_bf16.h>
#include <cstdint>
#include <cstddef>

#define M_DIM 16384
#define K_DIM 4096
#define N_DIM 4096

#define BM 128
#define BN 256
// BK in elements per stage = 32 bf16 = 64 bytes of K per row per stage
#define BK 32
#define KITERS (K_DIM / BK)   // 128
#define NSTAGES 4

// smem tile rows padded to 80 B: 16B-aligned; for 8-row x 16B ldmatrix phases
// bank offsets (20*r mod 32) = {0,20,8,28,16,4,24,12}, each +0..3 -> all 32
// banks exactly once -> conflict-free LDSM.
#define ROW_PITCH 80
#define A_BYTES (BM * ROW_PITCH)                 // 10240
#define B_BYTES (BN * ROW_PITCH)                 // 20480
#define STAGE_BYTES (A_BYTES + B_BYTES)          // 30720
#define GEMM_SMEM (NSTAGES * STAGE_BYTES)        // 122880

static_assert(M_DIM % BM == 0 && N_DIM % BN == 0 && K_DIM % BK == 0, "tiling");

// Scratch (allocation-free rule: __device__ globals). bf16 quantized values.
__device__ __nv_bfloat16 g_xq[(size_t)M_DIM * K_DIM];   // 128 MB
__device__ __nv_bfloat16 g_wq[(size_t)N_DIM * K_DIM];   // 32 MB
__device__ float g_xs[M_DIM];
__device__ float g_ws[N_DIM];
__device__ int   g_dtype;                                // 0=f16, 1=bf16, 2=f32

// ---------------- PTX helpers ----------------
__device__ __forceinline__ uint32_t smem_u32(const void* p) {
    uint32_t a;
    asm("{ .reg .u64 t; cvta.to.shared.u64 t, %1; cvt.u32.u64 %0, t; }" : "=r"(a) : "l"(p));
    return a;
}
__device__ __forceinline__ void cp16(uint32_t dst, const void* src) {
    asm volatile("cp.async.cg.shared.global [%0], [%1], 16;" :: "r"(dst), "l"(src));
}
__device__ __forceinline__ void ldsm_x4(uint32_t* r, uint32_t addr) {
    asm volatile("ldmatrix.sync.aligned.m8n8.x4.shared.b16 {%0,%1,%2,%3}, [%4];"
                 : "=r"(r[0]), "=r"(r[1]), "=r"(r[2]), "=r"(r[3]) : "r"(addr));
}
// bf16 MMA: m16n8k16, f32 accum.
__device__ __forceinline__ void mma_bf16(float* c, const uint32_t* a, uint32_t b0, uint32_t b1) {
    asm volatile(
        "mma.sync.aligned.m16n8k16.row.col.f32.bf16.bf16.f32 "
        "{%0,%1,%2,%3}, {%4,%5,%6,%7}, {%8,%9}, {%0,%1,%2,%3};"
        : "+f"(c[0]), "+f"(c[1]), "+f"(c[2]), "+f"(c[3])
        : "r"(a[0]), "r"(a[1]), "r"(a[2]), "r"(a[3]), "r"(b0), "r"(b1));
}

// ---------------- input dtype detection ----------------
__device__ __forceinline__ int plausible(float v) {
    return (isfinite(v) && fabsf(v) <= 64.0f && (v == 0.0f || fabsf(v) >= 1e-4f)) ? 1 : 0;
}

__global__ void detect_dtype_kernel(const void* __restrict__ x) {
    __shared__ int cnt[3];
    const int tid = threadIdx.x;
    if (tid < 3) cnt[tid] = 0;
    __syncthreads();
    int c0 = 0, c1 = 0, c2 = 0;
    const __half* ph = (const __half*)x;
    const __nv_bfloat16* pb = (const __nv_bfloat16*)x;
    const float* pf = (const float*)x;
    #pragma unroll
    for (int i = 0; i < 16; ++i) {
        int idx = tid * 16 + i;
        c0 += plausible(__half2float(ph[idx]));
        c1 += plausible(__bfloat162float(pb[idx]));
        c2 += plausible(pf[idx]);
    }
    atomicAdd(&cnt[0], c0); atomicAdd(&cnt[1], c1); atomicAdd(&cnt[2], c2);
    __syncthreads();
    if (tid == 0) {
        int best = 0;
        if (cnt[1] > cnt[best]) best = 1;
        if (cnt[2] > cnt[best]) best = 2;
        g_dtype = best;
    }
}

// ---------------- quantization (bit-exact match to reference) ----------------
__device__ __forceinline__ void load16(const void* __restrict__ in, size_t row,
                                       int tid, int dt, float* __restrict__ f) {
    if (dt == 2) {
        const float4* rp = reinterpret_cast<const float4*>((const float*)in + row * K_DIM);
        #pragma unroll
        for (int i = 0; i < 4; ++i) {
            float4 v = rp[4 * tid + i];
            f[4 * i + 0] = v.x; f[4 * i + 1] = v.y; f[4 * i + 2] = v.z; f[4 * i + 3] = v.w;
        }
    } else if (dt == 0) {
        const uint4* rp = reinterpret_cast<const uint4*>((const __half*)in + row * K_DIM);
        uint4 va = rp[2 * tid], vb = rp[2 * tid + 1];
        uint32_t u[8] = {va.x, va.y, va.z, va.w, vb.x, vb.y, vb.z, vb.w};
        #pragma unroll
        for (int i = 0; i < 8; ++i) {
            float2 v = __half22float2(*reinterpret_cast<__half2*>(&u[i]));
            f[2 * i] = v.x; f[2 * i + 1] = v.y;
        }
    } else {
        const uint4* rp = reinterpret_cast<const uint4*>((const __nv_bfloat16*)in + row * K_DIM);
        uint4 va = rp[2 * tid], vb = rp[2 * tid + 1];
        uint32_t u[8] = {va.x, va.y, va.z, va.w, vb.x, vb.y, vb.z, vb.w};
        #pragma unroll
        for (int i = 0; i < 8; ++i) {
            __nv_bfloat162 b = *reinterpret_cast<__nv_bfloat162*>(&u[i]);
            f[2 * i] = __bfloat162float(b.x); f[2 * i + 1] = __bfloat162float(b.y);
        }
    }
}

__device__ __forceinline__ void quant_row(const void* __restrict__ in,
                                          __nv_bfloat16* __restrict__ outq,
                                          float* __restrict__ scales) {
    const size_t row = blockIdx.x;
    const int tid = threadIdx.x;
    const int dt = g_dtype;

    float f[16];
    load16(in, row, tid, dt, f);

    float amax = 0.0f;
    #pragma unroll
    for (int i = 0; i < 16; ++i) amax = fmaxf(amax, fabsf(f[i]));
    #pragma unroll
    for (int o = 16; o > 0; o >>= 1)
        amax = fmaxf(amax, __shfl_xor_sync(0xffffffffu, amax, o));

    __shared__ float wmax[8];
    if ((tid & 31) == 0) wmax[tid >> 5] = amax;
    __syncthreads();
    float m = fmaxf(fmaxf(fmaxf(wmax[0], wmax[1]), fmaxf(wmax[2], wmax[3])),
                    fmaxf(fmaxf(wmax[4], wmax[5]), fmaxf(wmax[6], wmax[7])));
    // exact IEEE ops to match jnp: scale = max(absmax/7, 1e-8)
    const float scale = fmaxf(__fdiv_rn(m, 7.0f), 1e-8f);
    if (tid == 0) scales[row] = scale;

    // quantized integers in [-8,7] -> exact bf16
    uint32_t u[8];
    #pragma unroll
    for (int i = 0; i < 8; ++i) {
        float qa = fminf(7.0f, fmaxf(-8.0f, rintf(__fdiv_rn(f[2 * i], scale))));
        float qb = fminf(7.0f, fmaxf(-8.0f, rintf(__fdiv_rn(f[2 * i + 1], scale))));
        __nv_bfloat162 b = __floats2bfloat162_rn(qa, qb);
        u[i] = *reinterpret_cast<uint32_t*>(&b);
    }
    uint4* qp = reinterpret_cast<uint4*>(outq + row * K_DIM);
    qp[2 * tid]     = make_uint4(u[0], u[1], u[2], u[3]);
    qp[2 * tid + 1] = make_uint4(u[4], u[5], u[6], u[7]);
}

__global__ void quant_x_kernel(const void* __restrict__ x) { quant_row(x, g_xq, g_xs); }
__global__ void quant_w_kernel(const void* __restrict__ w) { quant_row(w, g_wq, g_ws); }

// ---------------- GEMM (HMMA bf16 m16n8k16, 64x64 warp tile) ----------------
// Stage layout: per row 32 bf16 = 64 bytes (4 x 16B chunks), pitch 80 B.
__device__ __forceinline__ void load_stage(uint32_t s_a, int tid,
                                           const __nv_bfloat16* __restrict__ Ag,
                                           const __nv_bfloat16* __restrict__ Bg) {
    const uint32_t s_b = s_a + A_BYTES;
    #pragma unroll
    for (int i = 0; i < (BM * 4) / 256; ++i) {   // 512 chunks
        int idx = tid + i * 256;
        int r = idx >> 2, c = idx & 3;   // chunk c = 8 bf16 elements
        cp16(s_a + (uint32_t)(r * ROW_PITCH + c * 16), Ag + (size_t)r * K_DIM + c * 8);
    }
    #pragma unroll
    for (int i = 0; i < (BN * 4) / 256; ++i) {   // 1024 chunks
        int idx = tid + i * 256;
        int r = idx >> 2, c = idx & 3;
        cp16(s_b + (uint32_t)(r * ROW_PITCH + c * 16), Bg + (size_t)r * K_DIM + c * 8);
    }
    asm volatile("cp.async.commit_group;");
}

__global__ void __launch_bounds__(256, 1)
gemm_kernel(const float* __restrict__ bias, float* __restrict__ out) {
    extern __shared__ char smem[];
    const uint32_t sbase = smem_u32(smem);
    const int tid  = threadIdx.x;
    const int wid  = tid >> 5;
    const int lane = tid & 31;
    const int warp_m = wid >> 2;      // 0..1 -> 64-row tile
    const int warp_n = wid & 3;       // 0..3 -> 64-col tile
    const int m0 = blockIdx.y * BM;
    const int n0 = blockIdx.x * BN;

    const __nv_bfloat16* Ag = g_xq + (size_t)m0 * K_DIM;
    const __nv_bfloat16* Bg = g_wq + (size_t)n0 * K_DIM;

    // ldmatrix x4 addresses (byte offsets within stage):
    // A (m16 x k16 tile mf): lane -> row (lane&15), kbyte (lane>>4)*16
    uint32_t aoff[4];
    #pragma unroll
    for (int mf = 0; mf < 4; ++mf)
        aoff[mf] = (uint32_t)((warp_m * 64 + mf * 16 + (lane & 15)) * ROW_PITCH
                              + (lane >> 4) * 16);
    // B (two n8 tiles per x4): lane -> n = nf2*16 + ((lane>>4)&1)*8 + (lane&7),
    // kbyte ((lane>>3)&1)*16 => r0,r1 = b0,b1 of tile nA ; r2,r3 = tile nB
    uint32_t boff[4];
    #pragma unroll
    for (int nf2 = 0; nf2 < 4; ++nf2)
        boff[nf2] = (uint32_t)(A_BYTES
                               + (warp_n * 64 + nf2 * 16 + ((lane >> 4) & 1) * 8 + (lane & 7))
                                 * ROW_PITCH
                               + ((lane >> 3) & 1) * 16);

    float acc[4][8][4];
    #pragma unroll
    for (int mf = 0; mf < 4; ++mf)
        #pragma unroll
        for (int nf = 0; nf < 8; ++nf)
            #pragma unroll
            for (int v = 0; v < 4; ++v) acc[mf][nf][v] = 0.0f;

    // prologue: fill 3 stages
    #pragma unroll
    for (int s = 0; s < NSTAGES - 1; ++s)
        load_stage(sbase + s * STAGE_BYTES, tid, Ag + (size_t)s * BK, Bg + (size_t)s * BK);

    #pragma unroll 1
    for (int i = 0; i < KITERS; ++i) {
        if (i < KITERS - 2)       asm volatile("cp.async.wait_group 2;");
        else if (i == KITERS - 2) asm volatile("cp.async.wait_group 1;");
        else                      asm volatile("cp.async.wait_group 0;");
        __syncthreads();

        const uint32_t st = sbase + (uint32_t)((i & (NSTAGES - 1)) * STAGE_BYTES);
        #pragma unroll
        for (int ks = 0; ks < 2; ++ks) {      // ks covers 16 elems = 32 bytes
            uint32_t a[4][4], b[4][4];
            #pragma unroll
            for (int mf = 0; mf < 4; ++mf) ldsm_x4(a[mf], st + aoff[mf] + ks * 32);
            #pragma unroll
            for (int nf2 = 0; nf2 < 4; ++nf2) ldsm_x4(b[nf2], st + boff[nf2] + ks * 32);
            #pragma unroll
            for (int nf = 0; nf < 8; ++nf) {
                const uint32_t b0 = b[nf >> 1][(nf & 1) * 2];
                const uint32_t b1 = b[nf >> 1][(nf & 1) * 2 + 1];
                #pragma unroll
                for (int mf = 0; mf < 4; ++mf)
                    mma_bf16(acc[mf][nf], a[mf], b0, b1);
            }
        }

        const int nxt = i + NSTAGES - 1;
        if (nxt < KITERS)
            load_stage(sbase + (uint32_t)(nxt & (NSTAGES - 1)) * STAGE_BYTES, tid,
                       Ag + (size_t)nxt * BK, Bg + (size_t)nxt * BK);
    }

    // epilogue: acc holds the exact integer dot product as f32.
    // match reference rounding exactly: ((acc*xs)*ws)+bias, no FMA contraction
    const int gid = lane >> 2, tig = lane & 3;
    #pragma unroll
    for (int mf = 0; mf < 4; ++mf) {
        const int r0 = m0 + warp_m * 64 + mf * 16 + gid;
        const float xs0 = g_xs[r0];
        const float xs1 = g_xs[r0 + 8];
        #pragma unroll
        for (int nf = 0; nf < 8; ++nf) {
            const int c = n0 + warp_n * 64 + nf * 8 + tig * 2;
            const float2 wsv = *reinterpret_cast<const float2*>(g_ws + c);
            const float2 bv  = *reinterpret_cast<const float2*>(bias + c);
            float2 o0, o1;
            o0.x = __fadd_rn(__fmul_rn(__fmul_rn(acc[mf][nf][0], xs0), wsv.x), bv.x);
            o0.y = __fadd_rn(__fmul_rn(__fmul_rn(acc[mf][nf][1], xs0), wsv.y), bv.y);
            o1.x = __fadd_rn(__fmul_rn(__fmul_rn(acc[mf][nf][2], xs1), wsv.x), bv.x);
            o1.y = __fadd_rn(__fmul_rn(__fmul_rn(acc[mf][nf][3], xs1), wsv.y), bv.y);
            *reinterpret_cast<float2*>(out + (size_t)r0 * N_DIM + c) = o0;
            *reinterpret_cast<float2*>(out + (size_t)(r0 + 8) * N_DIM + c) = o1;
        }
    }
}

// ---------------- launcher ----------------
extern "C" void kernel_launch(void* const* d_in, const int* in_sizes, int n_in,
                              void* d_out, int out_size) {
    (void)out_size;
    const void* x = nullptr;
    const void* w = nullptr;
    const float* bias = nullptr;
    for (int i = 0; i < n_in; ++i) {
        if (in_sizes[i] == M_DIM * K_DIM)      x    = d_in[i];
        else if (in_sizes[i] == N_DIM * K_DIM) w    = d_in[i];
        else if (in_sizes[i] == N_DIM)         bias = (const float*)d_in[i];
    }
    float* out = (float*)d_out;

    cudaFuncSetAttribute(gemm_kernel, cudaFuncAttributeMaxDynamicSharedMemorySize, GEMM_SMEM);

    detect_dtype_kernel<<<1, 256>>>(x);
    quant_x_kernel<<<M_DIM, 256>>>(x);
    quant_w_kernel<<<N_DIM, 256>>>(w);
    gemm_kernel<<<dim3(N_DIM / BN, M_DIM / BM), 256, GEMM_SMEM>>>(bias, out);
}

// round 15
// speedup vs baseline: 1.2030x; 1.2030x over previous
#include <cuda_runtime.h>
#include <cuda_fp16.h>
#include <cuda_bf16.h>
#include <cstdint>
#include <cstddef>

#define M_DIM 16384
#define K_DIM 4096
#define N_DIM 4096

#define BM 128
#define BN 128
// BK in elements per mainloop iteration = 64 bf16 = 128 bytes of K per row
#define BK 64
#define KITERS (K_DIM / BK)   // 64
#define NSTAGES 3

// smem rows: 128 B of data padded to 144 B. Bank offset of row r start:
// (144r/4) mod 32 = 4r mod 32 -> {0,4,...,28}; each 16B phase chunk spans 4
// banks -> 8-row ldmatrix phase covers all 32 banks exactly once (no conflict).
#define ROW_PITCH 144
#define A_BYTES (BM * ROW_PITCH)                 // 18432
#define B_BYTES (BN * ROW_PITCH)                 // 18432
#define STAGE_BYTES (A_BYTES + B_BYTES)          // 36864
#define GEMM_SMEM (NSTAGES * STAGE_BYTES)        // 110592

static_assert(M_DIM % BM == 0 && N_DIM % BN == 0 && K_DIM % BK == 0, "tiling");

// Scratch (allocation-free rule: __device__ globals). bf16 quantized values.
__device__ __nv_bfloat16 g_xq[(size_t)M_DIM * K_DIM];   // 128 MB
__device__ __nv_bfloat16 g_wq[(size_t)N_DIM * K_DIM];   // 32 MB
__device__ float g_xs[M_DIM];
__device__ float g_ws[N_DIM];
__device__ int   g_dtype;                                // 0=f16, 1=bf16, 2=f32

// ---------------- PTX helpers ----------------
__device__ __forceinline__ uint32_t smem_u32(const void* p) {
    uint32_t a;
    asm("{ .reg .u64 t; cvta.to.shared.u64 t, %1; cvt.u32.u64 %0, t; }" : "=r"(a) : "l"(p));
    return a;
}
__device__ __forceinline__ void cp16(uint32_t dst, const void* src) {
    asm volatile("cp.async.cg.shared.global [%0], [%1], 16;" :: "r"(dst), "l"(src));
}
__device__ __forceinline__ void ldsm_x4(uint32_t* r, uint32_t addr) {
    asm volatile("ldmatrix.sync.aligned.m8n8.x4.shared.b16 {%0,%1,%2,%3}, [%4];"
                 : "=r"(r[0]), "=r"(r[1]), "=r"(r[2]), "=r"(r[3]) : "r"(addr));
}
// bf16 MMA: m16n8k16, f32 accum.
__device__ __forceinline__ void mma_bf16(float* c, const uint32_t* a, uint32_t b0, uint32_t b1) {
    asm volatile(
        "mma.sync.aligned.m16n8k16.row.col.f32.bf16.bf16.f32 "
        "{%0,%1,%2,%3}, {%4,%5,%6,%7}, {%8,%9}, {%0,%1,%2,%3};"
        : "+f"(c[0]), "+f"(c[1]), "+f"(c[2]), "+f"(c[3])
        : "r"(a[0]), "r"(a[1]), "r"(a[2]), "r"(a[3]), "r"(b0), "r"(b1));
}

// ---------------- input dtype detection ----------------
__device__ __forceinline__ int plausible(float v) {
    return (isfinite(v) && fabsf(v) <= 64.0f && (v == 0.0f || fabsf(v) >= 1e-4f)) ? 1 : 0;
}

__global__ void detect_dtype_kernel(const void* __restrict__ x) {
    __shared__ int cnt[3];
    const int tid = threadIdx.x;
    if (tid < 3) cnt[tid] = 0;
    __syncthreads();
    int c0 = 0, c1 = 0, c2 = 0;
    const __half* ph = (const __half*)x;
    const __nv_bfloat16* pb = (const __nv_bfloat16*)x;
    const float* pf = (const float*)x;
    #pragma unroll
    for (int i = 0; i < 16; ++i) {
        int idx = tid * 16 + i;
        c0 += plausible(__half2float(ph[idx]));
        c1 += plausible(__bfloat162float(pb[idx]));
        c2 += plausible(pf[idx]);
    }
    atomicAdd(&cnt[0], c0); atomicAdd(&cnt[1], c1); atomicAdd(&cnt[2], c2);
    __syncthreads();
    if (tid == 0) {
        int best = 0;
        if (cnt[1] > cnt[best]) best = 1;
        if (cnt[2] > cnt[best]) best = 2;
        g_dtype = best;
    }
}

// ---------------- quantization (bit-exact match to reference) ----------------
__device__ __forceinline__ void load16(const void* __restrict__ in, size_t row,
                                       int tid, int dt, float* __restrict__ f) {
    if (dt == 2) {
        const float4* rp = reinterpret_cast<const float4*>((const float*)in + row * K_DIM);
        #pragma unroll
        for (int i = 0; i < 4; ++i) {
            float4 v = rp[4 * tid + i];
            f[4 * i + 0] = v.x; f[4 * i + 1] = v.y; f[4 * i + 2] = v.z; f[4 * i + 3] = v.w;
        }
    } else if (dt == 0) {
        const uint4* rp = reinterpret_cast<const uint4*>((const __half*)in + row * K_DIM);
        uint4 va = rp[2 * tid], vb = rp[2 * tid + 1];
        uint32_t u[8] = {va.x, va.y, va.z, va.w, vb.x, vb.y, vb.z, vb.w};
        #pragma unroll
        for (int i = 0; i < 8; ++i) {
            float2 v = __half22float2(*reinterpret_cast<__half2*>(&u[i]));
            f[2 * i] = v.x; f[2 * i + 1] = v.y;
        }
    } else {
        const uint4* rp = reinterpret_cast<const uint4*>((const __nv_bfloat16*)in + row * K_DIM);
        uint4 va = rp[2 * tid], vb = rp[2 * tid + 1];
        uint32_t u[8] = {va.x, va.y, va.z, va.w, vb.x, vb.y, vb.z, vb.w};
        #pragma unroll
        for (int i = 0; i < 8; ++i) {
            __nv_bfloat162 b = *reinterpret_cast<__nv_bfloat162*>(&u[i]);
            f[2 * i] = __bfloat162float(b.x); f[2 * i + 1] = __bfloat162float(b.y);
        }
    }
}

__device__ __forceinline__ void quant_row(const void* __restrict__ in,
                                          __nv_bfloat16* __restrict__ outq,
                                          float* __restrict__ scales) {
    const size_t row = blockIdx.x;
    const int tid = threadIdx.x;
    const int dt = g_dtype;

    float f[16];
    load16(in, row, tid, dt, f);

    float amax = 0.0f;
    #pragma unroll
    for (int i = 0; i < 16; ++i) amax = fmaxf(amax, fabsf(f[i]));
    #pragma unroll
    for (int o = 16; o > 0; o >>= 1)
        amax = fmaxf(amax, __shfl_xor_sync(0xffffffffu, amax, o));

    __shared__ float wmax[8];
    if ((tid & 31) == 0) wmax[tid >> 5] = amax;
    __syncthreads();
    float m = fmaxf(fmaxf(fmaxf(wmax[0], wmax[1]), fmaxf(wmax[2], wmax[3])),
                    fmaxf(fmaxf(wmax[4], wmax[5]), fmaxf(wmax[6], wmax[7])));
    // exact IEEE ops to match jnp: scale = max(absmax/7, 1e-8)
    const float scale = fmaxf(__fdiv_rn(m, 7.0f), 1e-8f);
    if (tid == 0) scales[row] = scale;

    // quantized integers in [-8,7] -> exact bf16
    uint32_t u[8];
    #pragma unroll
    for (int i = 0; i < 8; ++i) {
        float qa = fminf(7.0f, fmaxf(-8.0f, rintf(__fdiv_rn(f[2 * i], scale))));
        float qb = fminf(7.0f, fmaxf(-8.0f, rintf(__fdiv_rn(f[2 * i + 1], scale))));
        __nv_bfloat162 b = __floats2bfloat162_rn(qa, qb);
        u[i] = *reinterpret_cast<uint32_t*>(&b);
    }
    uint4* qp = reinterpret_cast<uint4*>(outq + row * K_DIM);
    qp[2 * tid]     = make_uint4(u[0], u[1], u[2], u[3]);
    qp[2 * tid + 1] = make_uint4(u[4], u[5], u[6], u[7]);
}

__global__ void quant_x_kernel(const void* __restrict__ x) { quant_row(x, g_xq, g_xs); }
__global__ void quant_w_kernel(const void* __restrict__ w) { quant_row(w, g_wq, g_ws); }

// ---------------- GEMM (HMMA bf16 m16n8k16, BK=64/iter, 3-stage) ------------
// Stage layout: per row 64 bf16 = 128 bytes (8 x 16B chunks), pitch 144 B.
__device__ __forceinline__ void load_stage(uint32_t s_a, int tid,
                                           const __nv_bfloat16* __restrict__ Ag,
                                           const __nv_bfloat16* __restrict__ Bg) {
    const uint32_t s_b = s_a + A_BYTES;
    #pragma unroll
    for (int i = 0; i < (BM * 8) / 256; ++i) {   // 1024 chunks
        int idx = tid + i * 256;
        int r = idx >> 3, c = idx & 7;   // chunk c = 8 bf16 elements
        cp16(s_a + (uint32_t)(r * ROW_PITCH + c * 16), Ag + (size_t)r * K_DIM + c * 8);
    }
    #pragma unroll
    for (int i = 0; i < (BN * 8) / 256; ++i) {   // 1024 chunks
        int idx = tid + i * 256;
        int r = idx >> 3, c = idx & 7;
        cp16(s_b + (uint32_t)(r * ROW_PITCH + c * 16), Bg + (size_t)r * K_DIM + c * 8);
    }
    asm volatile("cp.async.commit_group;");
}

__global__ void __launch_bounds__(256, 2)
gemm_kernel(const float* __restrict__ bias, float* __restrict__ out) {
    extern __shared__ char smem[];
    const uint32_t sbase = smem_u32(smem);
    const int tid  = threadIdx.x;
    const int wid  = tid >> 5;
    const int lane = tid & 31;
    const int warp_m = wid >> 1;      // 0..3 -> 32-row tile
    const int warp_n = wid & 1;       // 0..1 -> 64-col tile
    const int m0 = blockIdx.y * BM;
    const int n0 = blockIdx.x * BN;

    const __nv_bfloat16* Ag = g_xq + (size_t)m0 * K_DIM;
    const __nv_bfloat16* Bg = g_wq + (size_t)n0 * K_DIM;

    // ldmatrix x4 addresses (byte offsets within stage):
    // A (m16 x k16 tile mf): lane -> row (lane&15), kbyte (lane>>4)*16
    uint32_t aoff[2];
    #pragma unroll
    for (int mf = 0; mf < 2; ++mf)
        aoff[mf] = (uint32_t)((warp_m * 32 + mf * 16 + (lane & 15)) * ROW_PITCH
                              + (lane >> 4) * 16);
    // B (two n8 tiles per x4): lane -> n = nf2*16 + ((lane>>4)&1)*8 + (lane&7),
    // kbyte ((lane>>3)&1)*16 => r0,r1 = b0,b1 of tile nA ; r2,r3 = tile nB
    uint32_t boff[4];
    #pragma unroll
    for (int nf2 = 0; nf2 < 4; ++nf2)
        boff[nf2] = (uint32_t)(A_BYTES
                               + (warp_n * 64 + nf2 * 16 + ((lane >> 4) & 1) * 8 + (lane & 7))
                                 * ROW_PITCH
                               + ((lane >> 3) & 1) * 16);

    float acc[2][8][4];
    #pragma unroll
    for (int mf = 0; mf < 2; ++mf)
        #pragma unroll
        for (int nf = 0; nf < 8; ++nf)
            #pragma unroll
            for (int v = 0; v < 4; ++v) acc[mf][nf][v] = 0.0f;

    // prologue: fill 2 stages
    #pragma unroll
    for (int s = 0; s < NSTAGES - 1; ++s)
        load_stage(sbase + s * STAGE_BYTES, tid, Ag + (size_t)s * BK, Bg + (size_t)s * BK);

    #pragma unroll 1
    for (int i = 0; i < KITERS; ++i) {
        if (i < KITERS - 1) { asm volatile("cp.async.wait_group 1;"); }
        else                { asm volatile("cp.async.wait_group 0;"); }
        __syncthreads();

        const uint32_t st = sbase + (uint32_t)((i % NSTAGES) * STAGE_BYTES);
        // 4 independent ks chains (16 K-elems = 32 B each): fresh regs per ks
        // let the scheduler overlap ldsm(ks+1) with mma(ks).
        #pragma unroll
        for (int ks = 0; ks < 4; ++ks) {
            uint32_t a[2][4], b[4][4];
            #pragma unroll
            for (int mf = 0; mf < 2; ++mf) ldsm_x4(a[mf], st + aoff[mf] + ks * 32);
            #pragma unroll
            for (int nf2 = 0; nf2 < 4; ++nf2) ldsm_x4(b[nf2], st + boff[nf2] + ks * 32);
            #pragma unroll
            for (int nf = 0; nf < 8; ++nf) {
                const uint32_t b0 = b[nf >> 1][(nf & 1) * 2];
                const uint32_t b1 = b[nf >> 1][(nf & 1) * 2 + 1];
                #pragma unroll
                for (int mf = 0; mf < 2; ++mf)
                    mma_bf16(acc[mf][nf], a[mf], b0, b1);
            }
        }

        const int nxt = i + NSTAGES - 1;
        if (nxt < KITERS)
            load_stage(sbase + (uint32_t)((nxt % NSTAGES) * STAGE_BYTES), tid,
                       Ag + (size_t)nxt * BK, Bg + (size_t)nxt * BK);
    }

    // epilogue: acc holds the exact integer dot product as f32.
    // match reference rounding exactly: ((acc*xs)*ws)+bias, no FMA contraction
    const int gid = lane >> 2, tig = lane & 3;
    #pragma unroll
    for (int mf = 0; mf < 2; ++mf) {
        const int r0 = m0 + warp_m * 32 + mf * 16 + gid;
        const float xs0 = g_xs[r0];
        const float xs1 = g_xs[r0 + 8];
        #pragma unroll
        for (int nf = 0; nf < 8; ++nf) {
            const int c = n0 + warp_n * 64 + nf * 8 + tig * 2;
            const float2 wsv = *reinterpret_cast<const float2*>(g_ws + c);
            const float2 bv  = *reinterpret_cast<const float2*>(bias + c);
            float2 o0, o1;
            o0.x = __fadd_rn(__fmul_rn(__fmul_rn(acc[mf][nf][0], xs0), wsv.x), bv.x);
            o0.y = __fadd_rn(__fmul_rn(__fmul_rn(acc[mf][nf][1], xs0), wsv.y), bv.y);
            o1.x = __fadd_rn(__fmul_rn(__fmul_rn(acc[mf][nf][2], xs1), wsv.x), bv.x);
            o1.y = __fadd_rn(__fmul_rn(__fmul_rn(acc[mf][nf][3], xs1), wsv.y), bv.y);
            *reinterpret_cast<float2*>(out + (size_t)r0 * N_DIM + c) = o0;
            *reinterpret_cast<float2*>(out + (size_t)(r0 + 8) * N_DIM + c) = o1;
        }
    }
}

// ---------------- launcher ----------------
extern "C" void kernel_launch(void* const* d_in, const int* in_sizes, int n_in,
                              void* d_out, int out_size) {
    (void)out_size;
    const void* x = nullptr;
    const void* w = nullptr;
    const float* bias = nullptr;
    for (int i = 0; i < n_in; ++i) {
        if (in_sizes[i] == M_DIM * K_DIM)      x    = d_in[i];
        else if (in_sizes[i] == N_DIM * K_DIM) w    = d_in[i];
        else if (in_sizes[i] == N_DIM)         bias = (const float*)d_in[i];
    }
    float* out = (float*)d_out;

    cudaFuncSetAttribute(gemm_kernel, cudaFuncAttributeMaxDynamicSharedMemorySize, GEMM_SMEM);

    detect_dtype_kernel<<<1, 256>>>(x);
    quant_x_kernel<<<M_DIM, 256>>>(x);
    quant_w_kernel<<<N_DIM, 256>>>(w);
    gemm_kernel<<<dim3(N_DIM / BN, M_DIM / BM), 256, GEMM_SMEM>>>(bias, out);
}